// round 4
// baseline (speedup 1.0000x reference)
#include <cuda_runtime.h>
#include <cstdint>
#include <math.h>

// Problem constants
#define T_TOK 16384
#define DIM   1024
#define DFF_  4096
#define NE    8
#define CAP   3277      // ceil(16384*1.6/8)
#define CAPP  3328      // CAP padded to 26*128
#define NSTD  0.02f

// GEMM tiling
#define BM 128
#define BN 128
#define BK 32

// ---------------- device scratch (allocation-free rule: __device__ globals) ----------------
__device__ uint8_t g_top0[T_TOK];
__device__ uint8_t g_top1[T_TOK];
__device__ uint8_t g_kept[NE * T_TOK];
__device__ int     g_cnt[NE];
__device__ int     g_list[NE * CAPP];
__device__ float   g_h[(size_t)NE * CAPP * DFF_];   // ~436 MB hidden activations

// ---------------- helpers ----------------
__device__ __forceinline__ uint32_t f2tf32(float x) {
    uint32_t r;
    asm("cvt.rna.tf32.f32 %0, %1;" : "=r"(r) : "f"(x));
    return r;
}
__device__ __forceinline__ void mma_tf32(float* c, const uint32_t* a, const uint32_t* b) {
    asm volatile(
        "mma.sync.aligned.m16n8k8.row.col.f32.tf32.tf32.f32 "
        "{%0,%1,%2,%3}, {%4,%5,%6,%7}, {%8,%9}, {%0,%1,%2,%3};"
        : "+f"(c[0]), "+f"(c[1]), "+f"(c[2]), "+f"(c[3])
        : "r"(a[0]), "r"(a[1]), "r"(a[2]), "r"(a[3]), "r"(b[0]), "r"(b[1]));
}
__device__ __forceinline__ float gelu_exact(float v) {
    return 0.5f * v * (1.0f + erff(v * 0.7071067811865475f));
}

// ---------------- 1) router: logits + noise, top-2 expert indices ----------------
__global__ void router_kernel(const float* __restrict__ x,
                              const float* __restrict__ noise,
                              const float* __restrict__ rw,
                              const float* __restrict__ rb) {
    __shared__ float srw[NE][DIM];   // 32 KB router weights
    int tid = threadIdx.x;
    for (int i = tid; i < NE * DIM; i += 256) ((float*)srw)[i] = rw[i];
    __syncthreads();

    int warp = tid >> 5, lane = tid & 31;
    int t = blockIdx.x * 8 + warp;
    const float4* xr = (const float4*)(x + (size_t)t * DIM);

    float acc[NE];
#pragma unroll
    for (int e = 0; e < NE; e++) acc[e] = 0.f;
    for (int i = lane; i < DIM / 4; i += 32) {
        float4 v = xr[i];
        int d = i * 4;
#pragma unroll
        for (int e = 0; e < NE; e++)
            acc[e] += v.x * srw[e][d] + v.y * srw[e][d + 1] +
                      v.z * srw[e][d + 2] + v.w * srw[e][d + 3];
    }
#pragma unroll
    for (int e = 0; e < NE; e++) {
#pragma unroll
        for (int off = 16; off > 0; off >>= 1)
            acc[e] += __shfl_xor_sync(0xffffffffu, acc[e], off);
    }
    if (lane == 0) {
        float best = -1e30f, sec = -1e30f;
        int bi = 0, si = 0;
#pragma unroll
        for (int e = 0; e < NE; e++) {
            float v = acc[e] + rb[e] + noise[(size_t)t * NE + e] * NSTD;
            if (v > best)      { sec = best; si = bi; best = v; bi = e; }
            else if (v > sec)  { sec = v; si = e; }
        }
        g_top0[t] = (uint8_t)bi;
        g_top1[t] = (uint8_t)si;
    }
}

// ---------------- 2) per-expert capacity scan: kept[e][t] = routed && rank < CAP ----------------
__global__ void kept_kernel() {
    int e = blockIdx.x, tid = threadIdx.x;
    if (tid == 0) g_cnt[e] = 0;   // zero winner counters for list_kernel
    __shared__ int s[256];
    int offset = 0;
    for (int base = 0; base < T_TOK; base += 256) {
        int t = base + tid;
        int r = (g_top0[t] == e || g_top1[t] == e) ? 1 : 0;
        s[tid] = r;
        __syncthreads();
        // Hillis-Steele inclusive scan
        for (int d = 1; d < 256; d <<= 1) {
            int v = (tid >= d) ? s[tid - d] : 0;
            __syncthreads();
            s[tid] += v;
            __syncthreads();
        }
        int rank = offset + s[tid] - r;   // exclusive rank in token order
        int total = s[255];
        __syncthreads();
        g_kept[e * T_TOK + t] = (uint8_t)(r && rank < CAP);
        offset += total;
    }
}

// ---------------- 3) winner per token + compact per-expert token lists ----------------
// Winner = highest expert index among kept experts of the token (later experts overwrite).
__global__ void list_kernel() {
    int t = blockIdx.x * 256 + threadIdx.x;
    int e0 = g_top0[t], e1 = g_top1[t];
    int hi = e0 > e1 ? e0 : e1;
    int lo = e0 > e1 ? e1 : e0;
    int w = -1;
    if (g_kept[hi * T_TOK + t])      w = hi;
    else if (g_kept[lo * T_TOK + t]) w = lo;
    if (w >= 0) {
        int p = atomicAdd(&g_cnt[w], 1);
        g_list[w * CAPP + p] = t;   // order nondeterministic; output rows distinct => deterministic
    }
}

// ---------------- 4/5) expert GEMMs, TF32 mma.sync, batched over experts via blockIdx.z ----------
// FIRST:  h[e][m][:] = gelu( gather(x,list)[m] @ w1[e] + b1[e] )     (K=1024, N=4096)
// SECOND: out[list[m]][:] =           h[e][m] @ w2[e] + b2[e]        (K=4096, N=1024)
template <bool FIRST, int KD, int ND>
__global__ void __launch_bounds__(256, 2)
moe_gemm(const float* __restrict__ Xin,
         const float* __restrict__ Wbase,
         const float* __restrict__ Bias,
         float* __restrict__ Out) {
    int e = blockIdx.z;
    int cnt = g_cnt[e];
    int m0 = blockIdx.x * BM;
    if (m0 >= cnt) return;
    int n0 = blockIdx.y * BN;
    const float* W    = Wbase + (size_t)e * KD * ND;
    const float* bias = Bias + (size_t)e * ND;

    __shared__ float As[BM][BK + 4];
    __shared__ float Bs[BK][BN + 4];

    int tid = threadIdx.x;
    int lane = tid & 31, warp = tid >> 5;
    int wm = warp & 3, wn = warp >> 2;     // 4x2 warp grid, warp tile 32x64

    // A loader: 4 passes of 32 rows x 8 float4
    int arow = tid >> 3;
    int acol = (tid & 7) * 4;
    const float* asrc[4];
#pragma unroll
    for (int p = 0; p < 4; p++) {
        int m = m0 + arow + p * 32;
        if (FIRST) {
            int tok = (m < cnt) ? g_list[e * CAPP + m] : 0;   // clamp: never index x OOB
            asrc[p] = Xin + (size_t)tok * KD + acol;
        } else {
            asrc[p] = g_h + ((size_t)e * CAPP + m) * KD + acol;  // m < CAPP always in-bounds
        }
    }
    // B loader: 4 passes of 8 rows x 32 float4
    int brow = tid >> 5;
    int bcol = lane * 4;
    const float* bsrc = W + (size_t)brow * ND + n0 + bcol;

    float c[2][8][4];
#pragma unroll
    for (int i = 0; i < 2; i++)
#pragma unroll
        for (int j = 0; j < 8; j++)
#pragma unroll
            for (int q = 0; q < 4; q++) c[i][j][q] = 0.f;

    for (int kt = 0; kt < KD; kt += BK) {
#pragma unroll
        for (int p = 0; p < 4; p++) {
            float4 v = *(const float4*)(asrc[p] + kt);
            int r = arow + p * 32;
            As[r][acol]     = __uint_as_float(f2tf32(v.x));
            As[r][acol + 1] = __uint_as_float(f2tf32(v.y));
            As[r][acol + 2] = __uint_as_float(f2tf32(v.z));
            As[r][acol + 3] = __uint_as_float(f2tf32(v.w));
        }
#pragma unroll
        for (int p = 0; p < 4; p++) {
            float4 v = *(const float4*)(bsrc + (size_t)(kt + p * 8) * ND);
            int r = brow + p * 8;
            Bs[r][bcol]     = __uint_as_float(f2tf32(v.x));
            Bs[r][bcol + 1] = __uint_as_float(f2tf32(v.y));
            Bs[r][bcol + 2] = __uint_as_float(f2tf32(v.z));
            Bs[r][bcol + 3] = __uint_as_float(f2tf32(v.w));
        }
        __syncthreads();
#pragma unroll
        for (int kk = 0; kk < BK; kk += 8) {
            uint32_t a[2][4];
#pragma unroll
            for (int i = 0; i < 2; i++) {
                int r = wm * 32 + i * 16 + (lane >> 2);
                int cc = kk + (lane & 3);
                a[i][0] = __float_as_uint(As[r][cc]);
                a[i][1] = __float_as_uint(As[r + 8][cc]);
                a[i][2] = __float_as_uint(As[r][cc + 4]);
                a[i][3] = __float_as_uint(As[r + 8][cc + 4]);
            }
            uint32_t b[8][2];
#pragma unroll
            for (int j = 0; j < 8; j++) {
                int col = wn * 64 + j * 8 + (lane >> 2);
                int kr = kk + (lane & 3);
                b[j][0] = __float_as_uint(Bs[kr][col]);
                b[j][1] = __float_as_uint(Bs[kr + 4][col]);
            }
#pragma unroll
            for (int i = 0; i < 2; i++)
#pragma unroll
                for (int j = 0; j < 8; j++)
                    mma_tf32(c[i][j], a[i], b[j]);
        }
        __syncthreads();
    }

    // epilogue
    int gr = lane >> 2, gc = (lane & 3) * 2;
#pragma unroll
    for (int i = 0; i < 2; i++) {
        int mb = m0 + wm * 32 + i * 16 + gr;
#pragma unroll
        for (int j = 0; j < 8; j++) {
            int n = n0 + wn * 64 + j * 8 + gc;
            float bv0 = bias[n], bv1 = bias[n + 1];
            if (FIRST) {
                float* C = g_h + (size_t)e * CAPP * (size_t)ND;
                float2 v0 = make_float2(gelu_exact(c[i][j][0] + bv0),
                                        gelu_exact(c[i][j][1] + bv1));
                float2 v1 = make_float2(gelu_exact(c[i][j][2] + bv0),
                                        gelu_exact(c[i][j][3] + bv1));
                *(float2*)&C[(size_t)mb * ND + n]       = v0;
                *(float2*)&C[(size_t)(mb + 8) * ND + n] = v1;
            } else {
                if (mb < cnt) {
                    int tok = g_list[e * CAPP + mb];
                    float2 v0 = make_float2(c[i][j][0] + bv0, c[i][j][1] + bv1);
                    *(float2*)&Out[(size_t)tok * ND + n] = v0;
                }
                if (mb + 8 < cnt) {
                    int tok = g_list[e * CAPP + mb + 8];
                    float2 v1 = make_float2(c[i][j][2] + bv0, c[i][j][3] + bv1);
                    *(float2*)&Out[(size_t)tok * ND + n] = v1;
                }
            }
        }
    }
}

// ---------------- launcher ----------------
extern "C" void kernel_launch(void* const* d_in, const int* in_sizes, int n_in,
                              void* d_out, int out_size) {
    const float* x   = (const float*)d_in[0];
    const float* noi = (const float*)d_in[1];
    const float* rw  = (const float*)d_in[2];
    const float* rb  = (const float*)d_in[3];
    const float* w1  = (const float*)d_in[4];
    const float* b1  = (const float*)d_in[5];
    const float* w2  = (const float*)d_in[6];
    const float* b2  = (const float*)d_in[7];
    float* out = (float*)d_out;

    router_kernel<<<T_TOK / 8, 256>>>(x, noi, rw, rb);
    kept_kernel<<<NE, 256>>>();
    list_kernel<<<T_TOK / 256, 256>>>();
    // dropped tokens (no winner) must be exactly zero; out is poisoned pre-timing
    cudaMemsetAsync(d_out, 0, (size_t)out_size * sizeof(float));
    moe_gemm<true,  DIM,  DFF_><<<dim3(CAPP / BM, DFF_ / BN, NE), 256>>>(x,       w1, b1, nullptr);
    moe_gemm<false, DFF_, DIM ><<<dim3(CAPP / BM, DIM  / BN, NE), 256>>>(nullptr, w2, b2, out);
}

// round 5
// speedup vs baseline: 1.0017x; 1.0017x over previous
#include <cuda_runtime.h>
#include <cstdint>
#include <math.h>

// Problem constants
#define T_TOK 16384
#define DIM   1024
#define DFF_  4096
#define NE    8
#define CAP   3277      // ceil(16384*1.6/8)
#define CAPP  3328      // CAP padded to 26*128
#define NSTD  0.02f

// GEMM tiling
#define BM 128
#define BN 128
#define BK 32

// ---------------- device scratch (allocation-free rule: __device__ globals) ----------------
__device__ uint8_t g_top0[T_TOK];
__device__ uint8_t g_top1[T_TOK];
__device__ uint8_t g_kept[NE * T_TOK];
__device__ int     g_cnt[NE];
__device__ int     g_list[NE * CAPP];
__device__ float   g_h[(size_t)NE * CAPP * DFF_];   // ~436 MB hidden activations

// ---------------- helpers ----------------
__device__ __forceinline__ uint32_t f2tf32(float x) {
    uint32_t r;
    asm("cvt.rna.tf32.f32 %0, %1;" : "=r"(r) : "f"(x));
    return r;
}
__device__ __forceinline__ void mma_tf32(float* c, const uint32_t* a, const uint32_t* b) {
    asm volatile(
        "mma.sync.aligned.m16n8k8.row.col.f32.tf32.tf32.f32 "
        "{%0,%1,%2,%3}, {%4,%5,%6,%7}, {%8,%9}, {%0,%1,%2,%3};"
        : "+f"(c[0]), "+f"(c[1]), "+f"(c[2]), "+f"(c[3])
        : "r"(a[0]), "r"(a[1]), "r"(a[2]), "r"(a[3]), "r"(b[0]), "r"(b[1]));
}
__device__ __forceinline__ float gelu_exact(float v) {
    return 0.5f * v * (1.0f + erff(v * 0.7071067811865475f));
}

// ---------------- 1) router: logits + noise, top-2 expert indices ----------------
__global__ void router_kernel(const float* __restrict__ x,
                              const float* __restrict__ noise,
                              const float* __restrict__ rw,
                              const float* __restrict__ rb) {
    __shared__ float srw[NE][DIM];   // 32 KB router weights
    int tid = threadIdx.x;
    for (int i = tid; i < NE * DIM; i += 256) ((float*)srw)[i] = rw[i];
    __syncthreads();

    int warp = tid >> 5, lane = tid & 31;
    int t = blockIdx.x * 8 + warp;
    const float4* xr = (const float4*)(x + (size_t)t * DIM);

    float acc[NE];
#pragma unroll
    for (int e = 0; e < NE; e++) acc[e] = 0.f;
    for (int i = lane; i < DIM / 4; i += 32) {
        float4 v = xr[i];
        int d = i * 4;
#pragma unroll
        for (int e = 0; e < NE; e++)
            acc[e] += v.x * srw[e][d] + v.y * srw[e][d + 1] +
                      v.z * srw[e][d + 2] + v.w * srw[e][d + 3];
    }
#pragma unroll
    for (int e = 0; e < NE; e++) {
#pragma unroll
        for (int off = 16; off > 0; off >>= 1)
            acc[e] += __shfl_xor_sync(0xffffffffu, acc[e], off);
    }
    if (lane == 0) {
        float best = -1e30f, sec = -1e30f;
        int bi = 0, si = 0;
#pragma unroll
        for (int e = 0; e < NE; e++) {
            float v = acc[e] + rb[e] + noise[(size_t)t * NE + e] * NSTD;
            if (v > best)      { sec = best; si = bi; best = v; bi = e; }
            else if (v > sec)  { sec = v; si = e; }
        }
        g_top0[t] = (uint8_t)bi;
        g_top1[t] = (uint8_t)si;
    }
}

// ---------------- 2) per-expert capacity scan: kept[e][t] = routed && rank < CAP ----------------
__global__ void kept_kernel() {
    int e = blockIdx.x, tid = threadIdx.x;
    if (tid == 0) g_cnt[e] = 0;   // zero winner counters for list_kernel
    __shared__ int s[256];
    int offset = 0;
    for (int base = 0; base < T_TOK; base += 256) {
        int t = base + tid;
        int r = (g_top0[t] == e || g_top1[t] == e) ? 1 : 0;
        s[tid] = r;
        __syncthreads();
        // Hillis-Steele inclusive scan
        for (int d = 1; d < 256; d <<= 1) {
            int v = (tid >= d) ? s[tid - d] : 0;
            __syncthreads();
            s[tid] += v;
            __syncthreads();
        }
        int rank = offset + s[tid] - r;   // exclusive rank in token order
        int total = s[255];
        __syncthreads();
        g_kept[e * T_TOK + t] = (uint8_t)(r && rank < CAP);
        offset += total;
    }
}

// ---------------- 3) winner per token + compact per-expert token lists ----------------
// Winner = highest expert index among kept experts of the token (later experts overwrite).
__global__ void list_kernel() {
    int t = blockIdx.x * 256 + threadIdx.x;
    int e0 = g_top0[t], e1 = g_top1[t];
    int hi = e0 > e1 ? e0 : e1;
    int lo = e0 > e1 ? e1 : e0;
    int w = -1;
    if (g_kept[hi * T_TOK + t])      w = hi;
    else if (g_kept[lo * T_TOK + t]) w = lo;
    if (w >= 0) {
        int p = atomicAdd(&g_cnt[w], 1);
        g_list[w * CAPP + p] = t;   // order nondeterministic; output rows distinct => deterministic
    }
}

// ---------------- 4/5) expert GEMMs, TF32 mma.sync, batched over experts via blockIdx.z ----------
// FIRST:  h[e][m][:] = gelu( gather(x,list)[m] @ w1[e] + b1[e] )     (K=1024, N=4096)
// SECOND: out[list[m]][:] =           h[e][m] @ w2[e] + b2[e]        (K=4096, N=1024)
template <bool FIRST, int KD, int ND>
__global__ void __launch_bounds__(256, 2)
moe_gemm(const float* __restrict__ Xin,
         const float* __restrict__ Wbase,
         const float* __restrict__ Bias,
         float* __restrict__ Out) {
    int e = blockIdx.z;
    int cnt = g_cnt[e];
    int m0 = blockIdx.x * BM;
    if (m0 >= cnt) return;
    int n0 = blockIdx.y * BN;
    const float* W    = Wbase + (size_t)e * KD * ND;
    const float* bias = Bias + (size_t)e * ND;

    __shared__ float As[BM][BK + 4];
    __shared__ float Bs[BK][BN + 4];

    int tid = threadIdx.x;
    int lane = tid & 31, warp = tid >> 5;
    int wm = warp & 3, wn = warp >> 2;     // 4x2 warp grid, warp tile 32x64

    // A loader: 4 passes of 32 rows x 8 float4
    int arow = tid >> 3;
    int acol = (tid & 7) * 4;
    const float* asrc[4];
#pragma unroll
    for (int p = 0; p < 4; p++) {
        int m = m0 + arow + p * 32;
        if (FIRST) {
            int tok = (m < cnt) ? g_list[e * CAPP + m] : 0;   // clamp: never index x OOB
            asrc[p] = Xin + (size_t)tok * KD + acol;
        } else {
            asrc[p] = g_h + ((size_t)e * CAPP + m) * KD + acol;  // m < CAPP always in-bounds
        }
    }
    // B loader: 4 passes of 8 rows x 32 float4
    int brow = tid >> 5;
    int bcol = lane * 4;
    const float* bsrc = W + (size_t)brow * ND + n0 + bcol;

    float c[2][8][4];
#pragma unroll
    for (int i = 0; i < 2; i++)
#pragma unroll
        for (int j = 0; j < 8; j++)
#pragma unroll
            for (int q = 0; q < 4; q++) c[i][j][q] = 0.f;

    for (int kt = 0; kt < KD; kt += BK) {
#pragma unroll
        for (int p = 0; p < 4; p++) {
            float4 v = *(const float4*)(asrc[p] + kt);
            int r = arow + p * 32;
            As[r][acol]     = __uint_as_float(f2tf32(v.x));
            As[r][acol + 1] = __uint_as_float(f2tf32(v.y));
            As[r][acol + 2] = __uint_as_float(f2tf32(v.z));
            As[r][acol + 3] = __uint_as_float(f2tf32(v.w));
        }
#pragma unroll
        for (int p = 0; p < 4; p++) {
            float4 v = *(const float4*)(bsrc + (size_t)(kt + p * 8) * ND);
            int r = brow + p * 8;
            Bs[r][bcol]     = __uint_as_float(f2tf32(v.x));
            Bs[r][bcol + 1] = __uint_as_float(f2tf32(v.y));
            Bs[r][bcol + 2] = __uint_as_float(f2tf32(v.z));
            Bs[r][bcol + 3] = __uint_as_float(f2tf32(v.w));
        }
        __syncthreads();
#pragma unroll
        for (int kk = 0; kk < BK; kk += 8) {
            uint32_t a[2][4];
#pragma unroll
            for (int i = 0; i < 2; i++) {
                int r = wm * 32 + i * 16 + (lane >> 2);
                int cc = kk + (lane & 3);
                a[i][0] = __float_as_uint(As[r][cc]);
                a[i][1] = __float_as_uint(As[r + 8][cc]);
                a[i][2] = __float_as_uint(As[r][cc + 4]);
                a[i][3] = __float_as_uint(As[r + 8][cc + 4]);
            }
            uint32_t b[8][2];
#pragma unroll
            for (int j = 0; j < 8; j++) {
                int col = wn * 64 + j * 8 + (lane >> 2);
                int kr = kk + (lane & 3);
                b[j][0] = __float_as_uint(Bs[kr][col]);
                b[j][1] = __float_as_uint(Bs[kr + 4][col]);
            }
#pragma unroll
            for (int i = 0; i < 2; i++)
#pragma unroll
                for (int j = 0; j < 8; j++)
                    mma_tf32(c[i][j], a[i], b[j]);
        }
        __syncthreads();
    }

    // epilogue
    int gr = lane >> 2, gc = (lane & 3) * 2;
#pragma unroll
    for (int i = 0; i < 2; i++) {
        int mb = m0 + wm * 32 + i * 16 + gr;
#pragma unroll
        for (int j = 0; j < 8; j++) {
            int n = n0 + wn * 64 + j * 8 + gc;
            float bv0 = bias[n], bv1 = bias[n + 1];
            if (FIRST) {
                float* C = g_h + (size_t)e * CAPP * (size_t)ND;
                float2 v0 = make_float2(gelu_exact(c[i][j][0] + bv0),
                                        gelu_exact(c[i][j][1] + bv1));
                float2 v1 = make_float2(gelu_exact(c[i][j][2] + bv0),
                                        gelu_exact(c[i][j][3] + bv1));
                *(float2*)&C[(size_t)mb * ND + n]       = v0;
                *(float2*)&C[(size_t)(mb + 8) * ND + n] = v1;
            } else {
                if (mb < cnt) {
                    int tok = g_list[e * CAPP + mb];
                    float2 v0 = make_float2(c[i][j][0] + bv0, c[i][j][1] + bv1);
                    *(float2*)&Out[(size_t)tok * ND + n] = v0;
                }
                if (mb + 8 < cnt) {
                    int tok = g_list[e * CAPP + mb + 8];
                    float2 v1 = make_float2(c[i][j][2] + bv0, c[i][j][3] + bv1);
                    *(float2*)&Out[(size_t)tok * ND + n] = v1;
                }
            }
        }
    }
}

// ---------------- launcher ----------------
extern "C" void kernel_launch(void* const* d_in, const int* in_sizes, int n_in,
                              void* d_out, int out_size) {
    const float* x   = (const float*)d_in[0];
    const float* noi = (const float*)d_in[1];
    const float* rw  = (const float*)d_in[2];
    const float* rb  = (const float*)d_in[3];
    const float* w1  = (const float*)d_in[4];
    const float* b1  = (const float*)d_in[5];
    const float* w2  = (const float*)d_in[6];
    const float* b2  = (const float*)d_in[7];
    float* out = (float*)d_out;

    router_kernel<<<T_TOK / 8, 256>>>(x, noi, rw, rb);
    kept_kernel<<<NE, 256>>>();
    list_kernel<<<T_TOK / 256, 256>>>();
    // dropped tokens (no winner) must be exactly zero; out is poisoned pre-timing
    cudaMemsetAsync(d_out, 0, (size_t)out_size * sizeof(float));
    moe_gemm<true,  DIM,  DFF_><<<dim3(CAPP / BM, DFF_ / BN, NE), 256>>>(x,       w1, b1, nullptr);
    moe_gemm<false, DFF_, DIM ><<<dim3(CAPP / BM, DIM  / BN, NE), 256>>>(nullptr, w2, b2, out);
}